// round 12
// baseline (speedup 1.0000x reference)
#include <cuda_runtime.h>
#include <cuda_fp16.h>
#include <math.h>
#include <stdint.h>

#define BB 2048
#define KK 256
#define AD 512
#define IN 768

#define TM 64
#define TN 64
#define TKC 64
#define NSTAGE 3
#define A_ST_B (TM * 128)
#define B_ST_B (TN * 128)
#define GEMM_SMEM (NSTAGE * (A_ST_B + B_ST_B))   // 49152 B

// ---------------- scratch ----------------
__device__ __half g_A1  [(size_t)BB * 1536];
__device__ __half g_W1s [(size_t)AD * 1536];
__device__ __half g_A2  [(size_t)BB * 1024];
__device__ __half g_B2p [(size_t)768 * 1024];
__device__ __half g_W2T2[(size_t)512 * 512];
__device__ __half g_Er2 [(size_t)512 * 512];
__device__ float  g_bias2p[768];
__device__ float  g_X2e[(size_t)BB * 256];
__device__ float  g_P  [(size_t)BB * 512];
// dataflow counters (zeroed by conv each call)
__device__ int g_cnt_prep;
__device__ int g_cnt1[32];
__device__ int g_cnt2[32];

// ---------------- helpers ----------------
__device__ __forceinline__ uint32_t smem_u32(const void* p) {
    uint32_t a;
    asm("{ .reg .u64 t; cvta.to.shared.u64 t, %1; cvt.u32.u64 %0, t; }" : "=r"(a) : "l"(p));
    return a;
}
#define CP_ASYNC16(dst, src) \
    asm volatile("cp.async.cg.shared.global [%0], [%1], 16;" :: "r"(dst), "l"(src) : "memory")
#define CP_COMMIT()  asm volatile("cp.async.commit_group;" ::: "memory")
#define CP_WAIT(n)   asm volatile("cp.async.wait_group %0;" :: "n"(n) : "memory")

__device__ __forceinline__ void ldsm_x4(uint32_t* r, uint32_t addr) {
    asm volatile("ldmatrix.sync.aligned.m8n8.x4.shared.b16 {%0,%1,%2,%3}, [%4];"
                 : "=r"(r[0]), "=r"(r[1]), "=r"(r[2]), "=r"(r[3]) : "r"(addr));
}
__device__ __forceinline__ void mma16816(float* c, const uint32_t* a, const uint32_t* b) {
    asm volatile(
        "mma.sync.aligned.m16n8k16.row.col.f32.f16.f16.f32 "
        "{%0,%1,%2,%3}, {%4,%5,%6,%7}, {%8,%9}, {%0,%1,%2,%3};"
        : "+f"(c[0]), "+f"(c[1]), "+f"(c[2]), "+f"(c[3])
        : "r"(a[0]), "r"(a[1]), "r"(a[2]), "r"(a[3]), "r"(b[0]), "r"(b[1]));
}
__device__ __forceinline__ uint32_t swz(int row, int seg) {
    return (uint32_t)(row * 128 + ((seg ^ (row & 7)) << 4));
}
__device__ __forceinline__ void split_store_A(float4 v, __half* d, int Koff) {
    __align__(8) __half hh[4], ll[4];
    hh[0] = __float2half_rn(v.x); ll[0] = __float2half_rn(v.x - __half2float(hh[0]));
    hh[1] = __float2half_rn(v.y); ll[1] = __float2half_rn(v.y - __half2float(hh[1]));
    hh[2] = __float2half_rn(v.z); ll[2] = __float2half_rn(v.z - __half2float(hh[2]));
    hh[3] = __float2half_rn(v.w); ll[3] = __float2half_rn(v.w - __half2float(hh[3]));
    *(uint2*)d          = *(uint2*)hh;
    *(uint2*)(d + Koff) = *(uint2*)ll;
}
__device__ __forceinline__ void split_store_B(float4 v, __half* d, int Koff) {
    __align__(8) __half hh[4];
    hh[0] = __float2half_rn(v.x); hh[1] = __float2half_rn(v.y);
    hh[2] = __float2half_rn(v.z); hh[3] = __float2half_rn(v.w);
    *(uint2*)d          = *(uint2*)hh;
    *(uint2*)(d + Koff) = *(uint2*)hh;
}

// ---------------- fused conversion kernel (+ counter zeroing) ----------------
#define QR0 (BB * IN / 4)            // 393216
#define QR1 (QR0 + 512 * 768 / 4)    // 491520
#define QR2 (QR1 + 256 * 512 / 4)    // 524288
#define QR3 (QR2 + 512 * 64)         // 557056
#define QR4 (QR3 + 512 * 64)         // 589824
#define QR5 (QR4 + 64)               // 589888
#define QTOT (QR5 + 80)              // 589968

__global__ __launch_bounds__(256) void conv_all(
    const float* __restrict__ E, const float* __restrict__ H, const float* __restrict__ Qm,
    const float* __restrict__ W1, const float* __restrict__ W2, const float* __restrict__ emb_r,
    const float* __restrict__ b2,
    __half* __restrict__ A1, __half* __restrict__ W1s, __half* __restrict__ B2p,
    __half* __restrict__ W2T2, __half* __restrict__ Er2, float* __restrict__ bias2p)
{
    const int q = blockIdx.x * 256 + threadIdx.x;
    if (q >= QTOT) return;
    if (q < QR0) {
        const int m = q / 192, c = (q % 192) * 4;
        const float* src = (c < 256) ? (E + m * 256 + c)
                         : (c < 512) ? (H + m * 256 + (c - 256))
                                     : (Qm + m * 256 + (c - 512));
        float4 v = *(const float4*)src;
        split_store_A(v, A1 + (size_t)m * 1536 + c, 768);
    } else if (q < QR1) {
        const int q2 = q - QR0;
        const int n = q2 / 192, k = (q2 % 192) * 4;
        float4 v = *(const float4*)(W1 + (size_t)n * 768 + k);
        split_store_B(v, W1s + (size_t)n * 1536 + k, 768);
    } else if (q < QR2) {
        const int q2 = q - QR1;
        const int n = q2 >> 7, k = (q2 & 127) * 4;
        float4 v = *(const float4*)(W2 + (size_t)(256 + n) * 512 + k);
        split_store_B(v, B2p + (size_t)n * 1024 + k, 512);
    } else if (q < QR3) {
        const int q2 = q - QR2;
        const int d = q2 >> 6, c0 = (q2 & 63) * 4;
        float4 v;
        v.x = W2[(size_t)(c0 + 0) * 512 + d];
        v.y = W2[(size_t)(c0 + 1) * 512 + d];
        v.z = W2[(size_t)(c0 + 2) * 512 + d];
        v.w = W2[(size_t)(c0 + 3) * 512 + d];
        split_store_B(v, W2T2 + (size_t)d * 512 + c0, 256);
    } else if (q < QR4) {
        const int q2 = q - QR3;
        const int n = q2 >> 6, k = (q2 & 63) * 4;
        float4 v = make_float4(0.f, 0.f, 0.f, 0.f);
        if (n < 500) v = *(const float4*)(emb_r + (size_t)n * 256 + k);
        split_store_A(v, Er2 + (size_t)n * 512 + k, 256);
    } else if (q < QR5) {
        const int q2 = q - QR4;
        float4 v = *(const float4*)(b2 + 256 + q2 * 4);
        *(float4*)(bias2p + q2 * 4) = v;
    } else {
        const int q2 = q - QR5;                 // zero counters
        if (q2 == 0) g_cnt_prep = 0;
        else if (q2 <= 32) g_cnt1[q2 - 1] = 0;
        else if (q2 <= 64) g_cnt2[q2 - 33] = 0;
    }
}

// ---------------- fused GEMMs + score, one launch ----------------
// bid   0.. 63 : prep  W3' = Er2 @ W2T2^T  -> B2p rows 256+  (+bias3)
// bid  64..319 : G1    X = relu(A1 @ W1s^T + b1) -> A2 split     [mblk-major]
// bid 320..703 : G2'   [X2e|P] = X @ B2p^T + bias2p              [mblk-major]
// bid 704..2751: score softmax row b = bid-704
__global__ __launch_bounds__(256, 4) void fused_all(
    const float* __restrict__ b1,
    const float* __restrict__ emb_e, const float* __restrict__ mask,
    const int* __restrict__ r_space, const int* __restrict__ e_space,
    const float* __restrict__ erf, const float* __restrict__ b2f,
    float* __restrict__ out_dist, float* __restrict__ out_ent, int write_ent)
{
    extern __shared__ char dsm[];
    const int bid = blockIdx.x;
    const int t = threadIdx.x;
    const int warp = t >> 5, lane = t & 31;

    // =================== SCORE PATH ===================
    if (bid >= 704) {
        const int b = bid - 704;
        float* x2e = (float*)dsm;
        float* sc  = x2e + 256;
        float* red = sc + 256;       // 24 floats

        // wait for G2' m-block of this row
        if (t == 0) {
            volatile int* c = &g_cnt2[b >> 6];
            while (*c < 12) __nanosleep(200);
        }
        __syncthreads();

        x2e[t] = g_X2e[b * 256 + t];
        const int   kidx = warp * 32 + lane;
        const int   eall = e_space[b * KK + kidx];
        const float mval = mask[b * KK + kidx];
        const unsigned validb = __ballot_sync(0xFFFFFFFFu, mval != 0.0f);
        __syncthreads();

        const float4 xa = *(const float4*)&x2e[lane * 4];
        const float4 xb = *(const float4*)&x2e[lane * 4 + 128];

        for (int i = 0; i < 32; i++) {
            const int k = warp * 32 + i;
            if ((validb >> i) & 1u) {
                const int e = __shfl_sync(0xFFFFFFFFu, eall, i);
                const float4* er = (const float4*)(emb_e + (size_t)e * 256);
                const float4 v0 = er[lane];
                const float4 v1 = er[lane + 32];
                float s = v0.x * xa.x + v0.y * xa.y + v0.z * xa.z + v0.w * xa.w
                        + v1.x * xb.x + v1.y * xb.y + v1.z * xb.z + v1.w * xb.w;
                #pragma unroll
                for (int o = 16; o; o >>= 1) s += __shfl_xor_sync(0xFFFFFFFFu, s, o);
                if (lane == 0) sc[k] = s;
            } else {
                if (lane == 0) sc[k] = 0.0f;
            }
        }
        __syncthreads();

        const int r = r_space[b * KK + t];
        float s = sc[t] + g_P[b * 512 + r] - (1.0f - mask[b * KK + t]) * 1e31f;

        float mx = s;
        #pragma unroll
        for (int o = 16; o; o >>= 1) mx = fmaxf(mx, __shfl_xor_sync(0xFFFFFFFFu, mx, o));
        if (lane == 0) red[warp] = mx;
        __syncthreads();
        float bm = red[0];
        #pragma unroll
        for (int w = 1; w < 8; w++) bm = fmaxf(bm, red[w]);

        const float p = expf(s - bm);
        float sum = p;
        #pragma unroll
        for (int o = 16; o; o >>= 1) sum += __shfl_xor_sync(0xFFFFFFFFu, sum, o);
        if (lane == 0) red[8 + warp] = sum;
        __syncthreads();
        float bs = 0.f;
        #pragma unroll
        for (int w = 0; w < 8; w++) bs += red[8 + w];

        const float dist = p / bs;
        out_dist[b * KK + t] = dist;

        float es = -dist * logf(dist + 1e-20f);
        #pragma unroll
        for (int o = 16; o; o >>= 1) es += __shfl_xor_sync(0xFFFFFFFFu, es, o);
        if (lane == 0) red[16 + warp] = es;
        __syncthreads();
        if (t == 0 && write_ent) {
            float tot = 0.f;
            #pragma unroll
            for (int w = 0; w < 8; w++) tot += red[16 + w];
            out_ent[b] = tot;
        }
        return;
    }

    // =================== GEMM PATH (8 warps, 64x64 tile) ===================
    const uint32_t smA = smem_u32(dsm);
    const uint32_t smB = smA + NSTAGE * A_ST_B;

    int mode, m0, n0, ldk, nchunks, mblk = 0;
    const __half *A, *Bm;
    if (bid < 64) {                              // prep
        mode = 3; m0 = (bid & 7) * 64; n0 = (bid >> 3) * 64;
        A = g_Er2; Bm = g_W2T2; ldk = 512; nchunks = 8;
    } else if (bid < 320) {                      // G1, mblk-major
        const int q = bid - 64;
        mode = 0; mblk = q >> 3; m0 = mblk * 64; n0 = (q & 7) * 64;
        A = g_A1; Bm = g_W1s; ldk = 1536; nchunks = 24;
    } else {                                     // G2', mblk-major
        const int q = bid - 320;
        mode = 1; mblk = q / 12; m0 = mblk * 64; n0 = (q % 12) * 64;
        A = g_A2; Bm = g_B2p; ldk = 1024; nchunks = 16;
        if (t == 0) {
            volatile int* c1 = &g_cnt1[mblk];
            while (*c1 < 8) __nanosleep(200);
            if (n0 >= 256) {
                volatile int* cp = &g_cnt_prep;
                while (*cp < 64) __nanosleep(200);
            }
        }
        __syncthreads();
    }

    const int wm = (warp >> 2) * 32;       // 0 or 32
    const int wn = (warp & 3) * 16;        // 0,16,32,48
    const int rA  = lane & 15;
    const int sA8 = (lane >> 4);
    const int rB  = (lane & 7) + ((lane >> 4) & 1) * 8;
    const int sB8 = ((lane >> 3) & 1);

    float acc[2][2][4] = {};

    auto load_stage = [&](int s, int chunk) {
        const size_t k0 = (size_t)chunk * TKC;
        const uint32_t dA = smA + s * A_ST_B;
        const uint32_t dB = smB + s * B_ST_B;
        #pragma unroll
        for (int i = 0; i < 2; i++) {
            int v = t + i * 256;
            int row = v >> 3, seg = v & 7;
            CP_ASYNC16(dA + swz(row, seg),
                       A + (size_t)(m0 + row) * ldk + k0 + seg * 8);
        }
        #pragma unroll
        for (int i = 0; i < 2; i++) {
            int v = t + i * 256;
            int row = v >> 3, seg = v & 7;
            CP_ASYNC16(dB + swz(row, seg),
                       Bm + (size_t)(n0 + row) * ldk + k0 + seg * 8);
        }
        CP_COMMIT();
    };

    load_stage(0, 0);
    load_stage(1, 1);

    for (int i = 0; i < nchunks; i++) {
        CP_WAIT(1);
        __syncthreads();
        if (i + 2 < nchunks) load_stage((i + 2) % NSTAGE, i + 2);
        else CP_COMMIT();

        const uint32_t sAst = smA + (i % NSTAGE) * A_ST_B;
        const uint32_t sBst = smB + (i % NSTAGE) * B_ST_B;
        #pragma unroll
        for (int ks = 0; ks < 4; ks++) {
            uint32_t a0[4], a1[4], b0[4];
            const int segK = ks * 2;
            ldsm_x4(a0, sAst + swz(wm +      rA, segK + sA8));
            ldsm_x4(a1, sAst + swz(wm + 16 + rA, segK + sA8));
            ldsm_x4(b0, sBst + swz(wn +      rB, segK + sB8));
            mma16816(acc[0][0], a0, b0 + 0);
            mma16816(acc[0][1], a0, b0 + 2);
            mma16816(acc[1][0], a1, b0 + 0);
            mma16816(acc[1][1], a1, b0 + 2);
        }
    }

    // epilogue
    #pragma unroll
    for (int mi = 0; mi < 2; mi++) {
        #pragma unroll
        for (int h = 0; h < 2; h++) {
            const int row = m0 + wm + 16 * mi + 8 * h + (lane >> 2);
            #pragma unroll
            for (int ni = 0; ni < 2; ni++) {
                const int col = n0 + wn + 8 * ni + 2 * (lane & 3);
                float v0 = acc[mi][ni][2 * h];
                float v1 = acc[mi][ni][2 * h + 1];
                if (mode == 0) {
                    v0 = fmaxf(v0 + __ldg(&b1[col]), 0.0f);
                    v1 = fmaxf(v1 + __ldg(&b1[col + 1]), 0.0f);
                    __half h0 = __float2half_rn(v0);
                    __half h1 = __float2half_rn(v1);
                    __half l0 = __float2half_rn(v0 - __half2float(h0));
                    __half l1 = __float2half_rn(v1 - __half2float(h1));
                    __half2 hh; hh.x = h0; hh.y = h1;
                    __half2 ll; ll.x = l0; ll.y = l1;
                    __half* r0 = g_A2 + (size_t)row * 1024 + col;
                    *(__half2*)(r0)       = hh;
                    *(__half2*)(r0 + 512) = ll;
                } else if (mode == 1) {
                    v0 += __ldg(&g_bias2p[col]);
                    v1 += __ldg(&g_bias2p[col + 1]);
                    if (col < 256)
                        *(float2*)(g_X2e + (size_t)row * 256 + col) = make_float2(v0, v1);
                    else
                        *(float2*)(g_P + (size_t)row * 512 + (col - 256)) = make_float2(v0, v1);
                } else {
                    __half2 hh;
                    hh.x = __float2half_rn(v0);
                    hh.y = __float2half_rn(v1);
                    __half* r0 = g_B2p + (size_t)(256 + row) * 1024 + col;
                    *(__half2*)(r0)       = hh;
                    *(__half2*)(r0 + 512) = hh;
                }
            }
        }
    }

    if (mode == 3 && n0 == 0) {       // bias3[j] = <emb_r[j,:256], b2[:256]>
        const int j = m0 + (t >> 2);
        const int qr = t & 3;
        float s = 0.0f;
        if (j < 500) {
            const float* er = erf + (size_t)j * 256 + qr * 64;
            const float* bb = b2f + qr * 64;
            #pragma unroll 4
            for (int c = 0; c < 64; c++) s += er[c] * bb[c];
        }
        s += __shfl_xor_sync(0xFFFFFFFFu, s, 1);
        s += __shfl_xor_sync(0xFFFFFFFFu, s, 2);
        if (qr == 0) g_bias2p[256 + j] = (j < 500) ? s : 0.0f;
    }

    // release: publish this tile
    __syncthreads();
    if (t == 0) {
        __threadfence();
        if (mode == 3)      atomicAdd(&g_cnt_prep, 1);
        else if (mode == 0) atomicAdd(&g_cnt1[mblk], 1);
        else                atomicAdd(&g_cnt2[mblk], 1);
    }
}

// ---------------- launcher ----------------
extern "C" void kernel_launch(void* const* d_in, const int* in_sizes, int n_in,
                              void* d_out, int out_size)
{
    const float* E     = (const float*)d_in[0];
    const float* H     = (const float*)d_in[1];
    const float* Q     = (const float*)d_in[2];
    const float* W1    = (const float*)d_in[3];
    const float* b1    = (const float*)d_in[4];
    const float* W2    = (const float*)d_in[5];
    const float* b2    = (const float*)d_in[6];
    const float* emb_r = (const float*)d_in[7];
    const float* emb_e = (const float*)d_in[8];
    const float* mask  = (const float*)d_in[9];
    const int*   r_sp  = (const int*)d_in[10];
    const int*   e_sp  = (const int*)d_in[11];
    float* out = (float*)d_out;

    __half *gA1, *gW1s, *gB2p, *gW2T2, *gEr2;
    float *gbias2p;
    cudaGetSymbolAddress((void**)&gA1,    g_A1);
    cudaGetSymbolAddress((void**)&gW1s,   g_W1s);
    cudaGetSymbolAddress((void**)&gB2p,   g_B2p);
    cudaGetSymbolAddress((void**)&gW2T2,  g_W2T2);
    cudaGetSymbolAddress((void**)&gEr2,   g_Er2);
    cudaGetSymbolAddress((void**)&gbias2p, g_bias2p);

    cudaFuncSetAttribute(fused_all, cudaFuncAttributeMaxDynamicSharedMemorySize, GEMM_SMEM);

    const int write_ent = (out_size >= BB * KK + BB) ? 1 : 0;

    conv_all<<<(QTOT + 255) / 256, 256>>>(E, H, Q, W1, W2, emb_r, b2,
                                          gA1, gW1s, gB2p, gW2T2, gEr2, gbias2p);

    fused_all<<<2752, 256, GEMM_SMEM>>>(b1, emb_e, mask, r_sp, e_sp,
                                        emb_r, b2,
                                        out, out + (size_t)BB * KK, write_ent);
}

// round 13
// speedup vs baseline: 1.1424x; 1.1424x over previous
#include <cuda_runtime.h>
#include <cuda_fp16.h>
#include <math.h>
#include <stdint.h>

#define BB 2048
#define KK 256
#define AD 512
#define IN 768
#define NUME 100000

#define TM 64
#define TN 64
#define TKC 64
#define NSTAGE 3
#define A_ST_B (TM * 128)
#define B_ST_B (TN * 128)
#define GEMM_SMEM (NSTAGE * (A_ST_B + B_ST_B))   // 49152 B

// ---------------- scratch (device globals: no allocs allowed) ----------------
__device__ __half g_A1 [(size_t)BB * 1536];   // split concat(E,H,Q)  [hi|lo]
__device__ __half g_W1s[(size_t)AD * 1536];   // split W1             [hi|hi]
__device__ __half g_A2 [(size_t)BB * 1024];   // split X (G1 out)
__device__ __half g_W2s[(size_t)AD * 1024];
__device__ __half g_A3 [(size_t)BB * 512];    // split X2[:, :256]
__device__ __half g_Ers[(size_t)512 * 512];   // split emb_r (rows 500..511 zero)
__device__ __half g_Ee [(size_t)NUME * 256];  // fp16 emb_e (51.2 MB)
__device__ float g_X2e[(size_t)BB * 256];     // X2[:, 256:512] fp32
__device__ float g_P  [(size_t)BB * 512];     // X2[:, :256] @ emb_r^T

// ---------------- helpers ----------------
__device__ __forceinline__ uint32_t smem_u32(const void* p) {
    uint32_t a;
    asm("{ .reg .u64 t; cvta.to.shared.u64 t, %1; cvt.u32.u64 %0, t; }" : "=r"(a) : "l"(p));
    return a;
}
#define CP_ASYNC16(dst, src) \
    asm volatile("cp.async.cg.shared.global [%0], [%1], 16;" :: "r"(dst), "l"(src) : "memory")
#define CP_COMMIT()  asm volatile("cp.async.commit_group;" ::: "memory")
#define CP_WAIT(n)   asm volatile("cp.async.wait_group %0;" :: "n"(n) : "memory")

__device__ __forceinline__ void ldsm_x4(uint32_t* r, uint32_t addr) {
    asm volatile("ldmatrix.sync.aligned.m8n8.x4.shared.b16 {%0,%1,%2,%3}, [%4];"
                 : "=r"(r[0]), "=r"(r[1]), "=r"(r[2]), "=r"(r[3]) : "r"(addr));
}
__device__ __forceinline__ void mma16816(float* c, const uint32_t* a, const uint32_t* b) {
    asm volatile(
        "mma.sync.aligned.m16n8k16.row.col.f32.f16.f16.f32 "
        "{%0,%1,%2,%3}, {%4,%5,%6,%7}, {%8,%9}, {%0,%1,%2,%3};"
        : "+f"(c[0]), "+f"(c[1]), "+f"(c[2]), "+f"(c[3])
        : "r"(a[0]), "r"(a[1]), "r"(a[2]), "r"(a[3]), "r"(b[0]), "r"(b[1]));
}
__device__ __forceinline__ uint32_t swz(int row, int seg) {
    return (uint32_t)(row * 128 + ((seg ^ (row & 7)) << 4));
}
__device__ __forceinline__ void split_store_A(float4 v, __half* d, int Koff) {
    __align__(8) __half hh[4], ll[4];
    hh[0] = __float2half_rn(v.x); ll[0] = __float2half_rn(v.x - __half2float(hh[0]));
    hh[1] = __float2half_rn(v.y); ll[1] = __float2half_rn(v.y - __half2float(hh[1]));
    hh[2] = __float2half_rn(v.z); ll[2] = __float2half_rn(v.z - __half2float(hh[2]));
    hh[3] = __float2half_rn(v.w); ll[3] = __float2half_rn(v.w - __half2float(hh[3]));
    *(uint2*)d          = *(uint2*)hh;
    *(uint2*)(d + Koff) = *(uint2*)ll;
}
__device__ __forceinline__ void split_store_B(float4 v, __half* d, int Koff) {
    __align__(8) __half hh[4];
    hh[0] = __float2half_rn(v.x); hh[1] = __float2half_rn(v.y);
    hh[2] = __float2half_rn(v.z); hh[3] = __float2half_rn(v.w);
    *(uint2*)d          = *(uint2*)hh;
    *(uint2*)(d + Koff) = *(uint2*)hh;
}

// ---------------- branch B: emb_e fp32 -> fp16 (streams under the GEMM chain) ----------------
__global__ __launch_bounds__(256) void conv_ee(const float* __restrict__ src,
                                               __half* __restrict__ dst)
{
    const size_t i = ((size_t)blockIdx.x * 256 + threadIdx.x) * 8;   // over 25.6M elems
    float4 a = *(const float4*)(src + i);
    float4 b = *(const float4*)(src + i + 4);
    __align__(16) __half h[8];
    h[0] = __float2half_rn(a.x); h[1] = __float2half_rn(a.y);
    h[2] = __float2half_rn(a.z); h[3] = __float2half_rn(a.w);
    h[4] = __float2half_rn(b.x); h[5] = __float2half_rn(b.y);
    h[6] = __float2half_rn(b.z); h[7] = __float2half_rn(b.w);
    *(uint4*)(dst + i) = *(uint4*)h;
}

// ---------------- fused conversion kernel (branch A head) ----------------
#define Q_R0 (BB * IN / 4)               // 393216
#define Q_R1 (Q_R0 + 512 * 768 / 4)      // 491520
#define Q_R2 (Q_R1 + 512 * 512 / 4)      // 557056
#define Q_TOT (Q_R2 + 512 * 256 / 4)     // 589824

__global__ __launch_bounds__(256) void conv_all(
    const float* __restrict__ E, const float* __restrict__ H, const float* __restrict__ Qm,
    const float* __restrict__ W1, const float* __restrict__ W2, const float* __restrict__ emb_r,
    __half* __restrict__ A1, __half* __restrict__ W1s,
    __half* __restrict__ W2s, __half* __restrict__ Ers)
{
    const int q = blockIdx.x * 256 + threadIdx.x;
    if (q < Q_R0) {
        const int m = q / 192, c = (q % 192) * 4;
        const float* src = (c < 256) ? (E + m * 256 + c)
                         : (c < 512) ? (H + m * 256 + (c - 256))
                                     : (Qm + m * 256 + (c - 512));
        float4 v = *(const float4*)src;
        split_store_A(v, A1 + (size_t)m * 1536 + c, 768);
    } else if (q < Q_R1) {
        const int q2 = q - Q_R0;
        const int n = q2 / 192, k = (q2 % 192) * 4;
        float4 v = *(const float4*)(W1 + (size_t)n * 768 + k);
        split_store_B(v, W1s + (size_t)n * 1536 + k, 768);
    } else if (q < Q_R2) {
        const int q2 = q - Q_R1;
        const int n = q2 / 128, k = (q2 % 128) * 4;
        float4 v = *(const float4*)(W2 + (size_t)n * 512 + k);
        split_store_B(v, W2s + (size_t)n * 1024 + k, 512);
    } else {
        const int q2 = q - Q_R2;
        const int n = q2 / 64, k = (q2 % 64) * 4;
        float4 v = make_float4(0.f, 0.f, 0.f, 0.f);
        if (n < 500) v = *(const float4*)(emb_r + (size_t)n * 256 + k);
        split_store_B(v, Ers + (size_t)n * 512 + k, 256);
    }
}

// ---------------- HMMA GEMM (round-8 proven) ----------------
// MODE 0: +b1, relu, split-store into g_A2 (W=512)
// MODE 1: +b2; cols<256 -> split into g_A3 (W=256); cols>=256 -> fp32 g_X2e
// MODE 2: fp32 -> g_P (stride 512)
template <int MODE>
__global__ __launch_bounds__(128) void gemm_mma(
    const __half* __restrict__ A, const __half* __restrict__ Bm,
    int ldk, int nchunks, const float* __restrict__ bias,
    __half* __restrict__ outs, float* __restrict__ outf)
{
    extern __shared__ __half sm[];
    const uint32_t smA = smem_u32(sm);
    const uint32_t smB = smA + NSTAGE * A_ST_B;

    const int t = threadIdx.x;
    const int warp = t >> 5, lane = t & 31;
    const int m0 = blockIdx.x * TM;
    const int n0 = blockIdx.y * TN;
    const int wm = (warp >> 1) * 32;
    const int wn = (warp & 1) * 32;

    const int rA  = lane & 15;
    const int sA8 = (lane >> 4);
    const int rB  = (lane & 7) + ((lane >> 4) & 1) * 8;
    const int sB8 = ((lane >> 3) & 1);

    float acc[2][4][4] = {};

    auto load_stage = [&](int s, int chunk) {
        const size_t k0 = (size_t)chunk * TKC;
        const uint32_t dA = smA + s * A_ST_B;
        const uint32_t dB = smB + s * B_ST_B;
        #pragma unroll
        for (int i = 0; i < 4; i++) {
            int v = t + i * 128;
            int row = v >> 3, seg = v & 7;
            CP_ASYNC16(dA + swz(row, seg),
                       A + (size_t)(m0 + row) * ldk + k0 + seg * 8);
        }
        #pragma unroll
        for (int i = 0; i < 4; i++) {
            int v = t + i * 128;
            int row = v >> 3, seg = v & 7;
            CP_ASYNC16(dB + swz(row, seg),
                       Bm + (size_t)(n0 + row) * ldk + k0 + seg * 8);
        }
        CP_COMMIT();
    };

    load_stage(0, 0);
    load_stage(1, 1);

    for (int i = 0; i < nchunks; i++) {
        CP_WAIT(1);
        __syncthreads();
        if (i + 2 < nchunks) load_stage((i + 2) % NSTAGE, i + 2);
        else CP_COMMIT();

        const uint32_t sAst = smA + (i % NSTAGE) * A_ST_B;
        const uint32_t sBst = smB + (i % NSTAGE) * B_ST_B;
        #pragma unroll
        for (int ks = 0; ks < 4; ks++) {
            uint32_t a0[4], a1[4], b0[4], b1[4];
            const int segK = ks * 2;
            ldsm_x4(a0, sAst + swz(wm +      rA, segK + sA8));
            ldsm_x4(a1, sAst + swz(wm + 16 + rA, segK + sA8));
            ldsm_x4(b0, sBst + swz(wn +      rB, segK + sB8));
            ldsm_x4(b1, sBst + swz(wn + 16 + rB, segK + sB8));
            #pragma unroll
            for (int mi = 0; mi < 2; mi++) {
                const uint32_t* aa = mi ? a1 : a0;
                mma16816(acc[mi][0], aa, b0 + 0);
                mma16816(acc[mi][1], aa, b0 + 2);
                mma16816(acc[mi][2], aa, b1 + 0);
                mma16816(acc[mi][3], aa, b1 + 2);
            }
        }
    }

    #pragma unroll
    for (int mi = 0; mi < 2; mi++) {
        #pragma unroll
        for (int h = 0; h < 2; h++) {
            const int row = m0 + wm + 16 * mi + 8 * h + (lane >> 2);
            #pragma unroll
            for (int j = 0; j < 4; j++) {
                const int col = n0 + wn + 8 * j + 2 * (lane & 3);
                float v0 = acc[mi][j][2 * h];
                float v1 = acc[mi][j][2 * h + 1];
                if (MODE == 2) {
                    *(float2*)(outf + (size_t)row * 512 + col) = make_float2(v0, v1);
                } else {
                    v0 += __ldg(&bias[col]);
                    v1 += __ldg(&bias[col + 1]);
                    if (MODE == 0) { v0 = fmaxf(v0, 0.0f); v1 = fmaxf(v1, 0.0f); }
                    if (MODE == 1 && col >= 256) {
                        *(float2*)(outf + (size_t)row * 256 + (col - 256)) = make_float2(v0, v1);
                    } else {
                        const int W = (MODE == 0) ? 512 : 256;
                        __half h0 = __float2half_rn(v0);
                        __half h1 = __float2half_rn(v1);
                        __half l0 = __float2half_rn(v0 - __half2float(h0));
                        __half l1 = __float2half_rn(v1 - __half2float(h1));
                        __half2 hh; hh.x = h0; hh.y = h1;
                        __half2 ll; ll.x = l0; ll.y = l1;
                        __half* r0 = outs + (size_t)row * (2 * W) + col;
                        *(__half2*)(r0)     = hh;
                        *(__half2*)(r0 + W) = ll;
                    }
                }
            }
        }
    }
}

// ---------------- score + softmax + entropy (fp16 gather, mask-skipped) ----------------
__global__ __launch_bounds__(256) void score_softmax(
    const float* __restrict__ X2e, const float* __restrict__ P,
    const __half* __restrict__ emb16, const float* __restrict__ mask,
    const int* __restrict__ r_space, const int* __restrict__ e_space,
    float* __restrict__ out_dist, float* __restrict__ out_ent, int write_ent)
{
    const int b = blockIdx.x;
    __shared__ float x2e[256];
    __shared__ float sc[KK];
    __shared__ float red1[8], red2[8], red3[8];
    const int t = threadIdx.x;
    const int warp = t >> 5, lane = t & 31;

    x2e[t] = X2e[b * 256 + t];
    const int   kidx = warp * 32 + lane;
    const int   eall = e_space[b * KK + kidx];
    const float mval = mask[b * KK + kidx];
    const unsigned validb = __ballot_sync(0xFFFFFFFFu, mval != 0.0f);
    __syncthreads();

    // lane owns elements [lane*8, lane*8+8)
    const float4 xa = *(const float4*)&x2e[lane * 8];
    const float4 xb = *(const float4*)&x2e[lane * 8 + 4];

    for (int i = 0; i < 32; i++) {
        const int k = warp * 32 + i;
        if ((validb >> i) & 1u) {
            const int e = __shfl_sync(0xFFFFFFFFu, eall, i);
            const uint4 hv = *(const uint4*)(emb16 + (size_t)e * 256 + lane * 8);
            float2 p0 = __half22float2(*(const __half2*)&hv.x);
            float2 p1 = __half22float2(*(const __half2*)&hv.y);
            float2 p2 = __half22float2(*(const __half2*)&hv.z);
            float2 p3 = __half22float2(*(const __half2*)&hv.w);
            float s = p0.x * xa.x + p0.y * xa.y + p1.x * xa.z + p1.y * xa.w
                    + p2.x * xb.x + p2.y * xb.y + p3.x * xb.z + p3.y * xb.w;
            #pragma unroll
            for (int o = 16; o; o >>= 1) s += __shfl_xor_sync(0xFFFFFFFFu, s, o);
            if (lane == 0) sc[k] = s;
        } else {
            if (lane == 0) sc[k] = 0.0f;
        }
    }
    __syncthreads();

    const int r = r_space[b * KK + t];
    float s = sc[t] + P[b * 512 + r] - (1.0f - mask[b * KK + t]) * 1e31f;

    float mx = s;
#pragma unroll
    for (int o = 16; o; o >>= 1) mx = fmaxf(mx, __shfl_xor_sync(0xFFFFFFFFu, mx, o));
    if (lane == 0) red1[warp] = mx;
    __syncthreads();
    float bm = red1[0];
#pragma unroll
    for (int w = 1; w < 8; w++) bm = fmaxf(bm, red1[w]);

    const float p = expf(s - bm);
    float sum = p;
#pragma unroll
    for (int o = 16; o; o >>= 1) sum += __shfl_xor_sync(0xFFFFFFFFu, sum, o);
    if (lane == 0) red2[warp] = sum;
    __syncthreads();
    float bs = 0.f;
#pragma unroll
    for (int w = 0; w < 8; w++) bs += red2[w];

    const float dist = p / bs;
    out_dist[b * KK + t] = dist;

    float es = -dist * logf(dist + 1e-20f);
#pragma unroll
    for (int o = 16; o; o >>= 1) es += __shfl_xor_sync(0xFFFFFFFFu, es, o);
    if (lane == 0) red3[warp] = es;
    __syncthreads();
    if (t == 0 && write_ent) {
        float tot = 0.f;
#pragma unroll
        for (int w = 0; w < 8; w++) tot += red3[w];
        out_ent[b] = tot;
    }
}

// ---------------- launcher (graph fork/join: emb_e convert ∥ GEMM chain) ----------------
extern "C" void kernel_launch(void* const* d_in, const int* in_sizes, int n_in,
                              void* d_out, int out_size)
{
    const float* E     = (const float*)d_in[0];
    const float* H     = (const float*)d_in[1];
    const float* Q     = (const float*)d_in[2];
    const float* W1    = (const float*)d_in[3];
    const float* b1    = (const float*)d_in[4];
    const float* W2    = (const float*)d_in[5];
    const float* b2    = (const float*)d_in[6];
    const float* emb_r = (const float*)d_in[7];
    const float* emb_e = (const float*)d_in[8];
    const float* mask  = (const float*)d_in[9];
    const int*   r_sp  = (const int*)d_in[10];
    const int*   e_sp  = (const int*)d_in[11];
    float* out = (float*)d_out;

    __half *gA1, *gW1s, *gA2, *gW2s, *gA3, *gErs, *gEe;
    float *gX2e, *gP;
    cudaGetSymbolAddress((void**)&gA1,  g_A1);
    cudaGetSymbolAddress((void**)&gW1s, g_W1s);
    cudaGetSymbolAddress((void**)&gA2,  g_A2);
    cudaGetSymbolAddress((void**)&gW2s, g_W2s);
    cudaGetSymbolAddress((void**)&gA3,  g_A3);
    cudaGetSymbolAddress((void**)&gErs, g_Ers);
    cudaGetSymbolAddress((void**)&gEe,  g_Ee);
    cudaGetSymbolAddress((void**)&gX2e, g_X2e);
    cudaGetSymbolAddress((void**)&gP,   g_P);

    cudaFuncSetAttribute(gemm_mma<0>, cudaFuncAttributeMaxDynamicSharedMemorySize, GEMM_SMEM);
    cudaFuncSetAttribute(gemm_mma<1>, cudaFuncAttributeMaxDynamicSharedMemorySize, GEMM_SMEM);
    cudaFuncSetAttribute(gemm_mma<2>, cudaFuncAttributeMaxDynamicSharedMemorySize, GEMM_SMEM);

    const int write_ent = (out_size >= BB * KK + BB) ? 1 : 0;

    // fork: branch B (emb_e -> fp16) runs concurrently with branch A (conv + GEMMs)
    cudaStream_t s2;
    cudaEvent_t evFork, evJoin;
    cudaStreamCreateWithFlags(&s2, cudaStreamNonBlocking);
    cudaEventCreateWithFlags(&evFork, cudaEventDisableTiming);
    cudaEventCreateWithFlags(&evJoin, cudaEventDisableTiming);

    cudaEventRecord(evFork, 0);
    cudaStreamWaitEvent(s2, evFork, 0);
    conv_ee<<<(NUME * 256) / (256 * 8), 256, 0, s2>>>(emb_e, gEe);   // 12500 blocks
    cudaEventRecord(evJoin, s2);

    conv_all<<<Q_TOT / 256, 256>>>(E, H, Q, W1, W2, emb_r, gA1, gW1s, gW2s, gErs);
    gemm_mma<0><<<dim3(BB / TM, AD / TN), 128, GEMM_SMEM>>>(gA1, gW1s, 1536, 24, b1, gA2, nullptr);
    gemm_mma<1><<<dim3(BB / TM, AD / TN), 128, GEMM_SMEM>>>(gA2, gW2s, 1024, 16, b2, gA3, gX2e);
    gemm_mma<2><<<dim3(BB / TM, AD / TN), 128, GEMM_SMEM>>>(gA3, gErs,  512,  8, nullptr, nullptr, gP);

    cudaStreamWaitEvent(0, evJoin, 0);
    score_softmax<<<BB, 256>>>(gX2e, gP, gEe, mask, r_sp, e_sp,
                               out, out + (size_t)BB * KK, write_ent);
}

// round 14
// speedup vs baseline: 1.2279x; 1.0749x over previous
#include <cuda_runtime.h>
#include <cuda_fp16.h>
#include <math.h>
#include <stdint.h>

#define BB 2048
#define KK 256
#define AD 512
#define IN 768

#define TM 64
#define TN 64
#define TKC 64
#define NSTAGE 3
#define A_ST_B (TM * 128)
#define B_ST_B (TN * 128)
#define GEMM_SMEM (NSTAGE * (A_ST_B + B_ST_B))   // 49152 B

// ---------------- scratch (device globals: no allocs allowed) ----------------
__device__ __half g_A1 [(size_t)BB * 1536];   // split concat(E,H,Q)  [hi|lo]
__device__ __half g_W1s[(size_t)AD * 1536];   // split W1             [hi|hi]
__device__ __half g_A2 [(size_t)BB * 1024];   // split X (G1 out)
__device__ __half g_W2s[(size_t)AD * 1024];
__device__ __half g_A3 [(size_t)BB * 512];    // split X2[:, :256]
__device__ __half g_Ers[(size_t)512 * 512];   // split emb_r (rows 500..511 zero)
__device__ float g_X2e[(size_t)BB * 256];     // X2[:, 256:512] fp32
__device__ float g_P  [(size_t)BB * 512];     // X2[:, :256] @ emb_r^T
// dataflow counters (zeroed by conv each call)
__device__ int g_c1[32];
__device__ int g_c2[32];

// ---------------- helpers ----------------
__device__ __forceinline__ uint32_t smem_u32(const void* p) {
    uint32_t a;
    asm("{ .reg .u64 t; cvta.to.shared.u64 t, %1; cvt.u32.u64 %0, t; }" : "=r"(a) : "l"(p));
    return a;
}
#define CP_ASYNC16(dst, src) \
    asm volatile("cp.async.cg.shared.global [%0], [%1], 16;" :: "r"(dst), "l"(src) : "memory")
#define CP_COMMIT()  asm volatile("cp.async.commit_group;" ::: "memory")
#define CP_WAIT(n)   asm volatile("cp.async.wait_group %0;" :: "n"(n) : "memory")

__device__ __forceinline__ void ldsm_x4(uint32_t* r, uint32_t addr) {
    asm volatile("ldmatrix.sync.aligned.m8n8.x4.shared.b16 {%0,%1,%2,%3}, [%4];"
                 : "=r"(r[0]), "=r"(r[1]), "=r"(r[2]), "=r"(r[3]) : "r"(addr));
}
__device__ __forceinline__ void mma16816(float* c, const uint32_t* a, const uint32_t* b) {
    asm volatile(
        "mma.sync.aligned.m16n8k16.row.col.f32.f16.f16.f32 "
        "{%0,%1,%2,%3}, {%4,%5,%6,%7}, {%8,%9}, {%0,%1,%2,%3};"
        : "+f"(c[0]), "+f"(c[1]), "+f"(c[2]), "+f"(c[3])
        : "r"(a[0]), "r"(a[1]), "r"(a[2]), "r"(a[3]), "r"(b[0]), "r"(b[1]));
}
__device__ __forceinline__ uint32_t swz(int row, int seg) {
    return (uint32_t)(row * 128 + ((seg ^ (row & 7)) << 4));
}
__device__ __forceinline__ void split_store_A(float4 v, __half* d, int Koff) {
    __align__(8) __half hh[4], ll[4];
    hh[0] = __float2half_rn(v.x); ll[0] = __float2half_rn(v.x - __half2float(hh[0]));
    hh[1] = __float2half_rn(v.y); ll[1] = __float2half_rn(v.y - __half2float(hh[1]));
    hh[2] = __float2half_rn(v.z); ll[2] = __float2half_rn(v.z - __half2float(hh[2]));
    hh[3] = __float2half_rn(v.w); ll[3] = __float2half_rn(v.w - __half2float(hh[3]));
    *(uint2*)d          = *(uint2*)hh;
    *(uint2*)(d + Koff) = *(uint2*)ll;
}
__device__ __forceinline__ void split_store_B(float4 v, __half* d, int Koff) {
    __align__(8) __half hh[4];
    hh[0] = __float2half_rn(v.x); hh[1] = __float2half_rn(v.y);
    hh[2] = __float2half_rn(v.z); hh[3] = __float2half_rn(v.w);
    *(uint2*)d          = *(uint2*)hh;
    *(uint2*)(d + Koff) = *(uint2*)hh;
}

// ---------------- fused conversion kernel (+ counter zeroing) ----------------
#define Q_R0 (BB * IN / 4)               // 393216
#define Q_R1 (Q_R0 + 512 * 768 / 4)      // 491520
#define Q_R2 (Q_R1 + 512 * 512 / 4)      // 557056
#define Q_R3 (Q_R2 + 512 * 256 / 4)      // 589824
#define Q_TOT (Q_R3 + 64)                // 589888

__global__ __launch_bounds__(256) void conv_all(
    const float* __restrict__ E, const float* __restrict__ H, const float* __restrict__ Qm,
    const float* __restrict__ W1, const float* __restrict__ W2, const float* __restrict__ emb_r,
    __half* __restrict__ A1, __half* __restrict__ W1s,
    __half* __restrict__ W2s, __half* __restrict__ Ers)
{
    const int q = blockIdx.x * 256 + threadIdx.x;
    if (q >= Q_TOT) return;
    if (q < Q_R0) {
        const int m = q / 192, c = (q % 192) * 4;
        const float* src = (c < 256) ? (E + m * 256 + c)
                         : (c < 512) ? (H + m * 256 + (c - 256))
                                     : (Qm + m * 256 + (c - 512));
        float4 v = *(const float4*)src;
        split_store_A(v, A1 + (size_t)m * 1536 + c, 768);
    } else if (q < Q_R1) {
        const int q2 = q - Q_R0;
        const int n = q2 / 192, k = (q2 % 192) * 4;
        float4 v = *(const float4*)(W1 + (size_t)n * 768 + k);
        split_store_B(v, W1s + (size_t)n * 1536 + k, 768);
    } else if (q < Q_R2) {
        const int q2 = q - Q_R1;
        const int n = q2 / 128, k = (q2 % 128) * 4;
        float4 v = *(const float4*)(W2 + (size_t)n * 512 + k);
        split_store_B(v, W2s + (size_t)n * 1024 + k, 512);
    } else if (q < Q_R3) {
        const int q2 = q - Q_R2;
        const int n = q2 / 64, k = (q2 % 64) * 4;
        float4 v = make_float4(0.f, 0.f, 0.f, 0.f);
        if (n < 500) v = *(const float4*)(emb_r + (size_t)n * 256 + k);
        split_store_B(v, Ers + (size_t)n * 512 + k, 256);
    } else {
        const int q2 = q - Q_R3;                 // zero counters
        if (q2 < 32) g_c1[q2] = 0;
        else g_c2[q2 - 32] = 0;
    }
}

// ---------------- merged GEMM chain: G1 -> G2 -> G3 in ONE launch ----------------
// bid   0..255: G1  X = relu(A1@W1s^T + b1) -> A-split g_A2          (24 chunks)
// bid 256..511: G2  X2 = X@W2s^T + b2; cols<256 -> A-split g_A3,
//                   cols>=256 -> fp32 g_X2e                          (16 chunks, waits c1)
// bid 512..767: G3  P = A3@Ers^T -> fp32 g_P                         (8 chunks,  waits c2)
__global__ __launch_bounds__(128) void gemm_fused(
    const float* __restrict__ b1, const float* __restrict__ b2)
{
    extern __shared__ __half sm[];
    const uint32_t smA = smem_u32(sm);
    const uint32_t smB = smA + NSTAGE * A_ST_B;

    const int bid = blockIdx.x;
    const int t = threadIdx.x;
    const int warp = t >> 5, lane = t & 31;

    int mode, mblk, n0, ldk, nchunks;
    const __half *A, *Bm;
    if (bid < 256) {
        mode = 0; mblk = bid >> 3; n0 = (bid & 7) * 64;
        A = g_A1; Bm = g_W1s; ldk = 1536; nchunks = 24;
    } else if (bid < 512) {
        const int q = bid - 256;
        mode = 1; mblk = q >> 3; n0 = (q & 7) * 64;
        A = g_A2; Bm = g_W2s; ldk = 1024; nchunks = 16;
        if (t == 0) {
            volatile int* c = &g_c1[mblk];
            while (*c < 8) __nanosleep(100);
        }
        __syncthreads();
        __threadfence();
    } else {
        const int q = bid - 512;
        mode = 2; mblk = q >> 3; n0 = (q & 7) * 64;
        A = g_A3; Bm = g_Ers; ldk = 512; nchunks = 8;
        if (t == 0) {
            volatile int* c = &g_c2[mblk];
            while (*c < 8) __nanosleep(100);
        }
        __syncthreads();
        __threadfence();
    }
    const int m0 = mblk * 64;

    const int wm = (warp >> 1) * 32;
    const int wn = (warp & 1) * 32;
    const int rA  = lane & 15;
    const int sA8 = (lane >> 4);
    const int rB  = (lane & 7) + ((lane >> 4) & 1) * 8;
    const int sB8 = ((lane >> 3) & 1);

    float acc[2][4][4] = {};

    auto load_stage = [&](int s, int chunk) {
        const size_t k0 = (size_t)chunk * TKC;
        const uint32_t dA = smA + s * A_ST_B;
        const uint32_t dB = smB + s * B_ST_B;
        #pragma unroll
        for (int i = 0; i < 4; i++) {
            int v = t + i * 128;
            int row = v >> 3, seg = v & 7;
            CP_ASYNC16(dA + swz(row, seg),
                       A + (size_t)(m0 + row) * ldk + k0 + seg * 8);
        }
        #pragma unroll
        for (int i = 0; i < 4; i++) {
            int v = t + i * 128;
            int row = v >> 3, seg = v & 7;
            CP_ASYNC16(dB + swz(row, seg),
                       Bm + (size_t)(n0 + row) * ldk + k0 + seg * 8);
        }
        CP_COMMIT();
    };

    load_stage(0, 0);
    load_stage(1, 1);

    for (int i = 0; i < nchunks; i++) {
        CP_WAIT(1);
        __syncthreads();
        if (i + 2 < nchunks) load_stage((i + 2) % NSTAGE, i + 2);
        else CP_COMMIT();

        const uint32_t sAst = smA + (i % NSTAGE) * A_ST_B;
        const uint32_t sBst = smB + (i % NSTAGE) * B_ST_B;
        #pragma unroll
        for (int ks = 0; ks < 4; ks++) {
            uint32_t a0[4], a1[4], b0[4], b1r[4];
            const int segK = ks * 2;
            ldsm_x4(a0, sAst + swz(wm +      rA, segK + sA8));
            ldsm_x4(a1, sAst + swz(wm + 16 + rA, segK + sA8));
            ldsm_x4(b0, sBst + swz(wn +      rB, segK + sB8));
            ldsm_x4(b1r, sBst + swz(wn + 16 + rB, segK + sB8));
            #pragma unroll
            for (int mi = 0; mi < 2; mi++) {
                const uint32_t* aa = mi ? a1 : a0;
                mma16816(acc[mi][0], aa, b0 + 0);
                mma16816(acc[mi][1], aa, b0 + 2);
                mma16816(acc[mi][2], aa, b1r + 0);
                mma16816(acc[mi][3], aa, b1r + 2);
            }
        }
    }

    // ---------------- epilogue ----------------
    #pragma unroll
    for (int mi = 0; mi < 2; mi++) {
        #pragma unroll
        for (int h = 0; h < 2; h++) {
            const int row = m0 + wm + 16 * mi + 8 * h + (lane >> 2);
            #pragma unroll
            for (int j = 0; j < 4; j++) {
                const int col = n0 + wn + 8 * j + 2 * (lane & 3);
                float v0 = acc[mi][j][2 * h];
                float v1 = acc[mi][j][2 * h + 1];
                if (mode == 2) {
                    *(float2*)(g_P + (size_t)row * 512 + col) = make_float2(v0, v1);
                } else if (mode == 0) {
                    v0 = fmaxf(v0 + __ldg(&b1[col]), 0.0f);
                    v1 = fmaxf(v1 + __ldg(&b1[col + 1]), 0.0f);
                    __half h0 = __float2half_rn(v0);
                    __half h1 = __float2half_rn(v1);
                    __half l0 = __float2half_rn(v0 - __half2float(h0));
                    __half l1 = __float2half_rn(v1 - __half2float(h1));
                    __half2 hh; hh.x = h0; hh.y = h1;
                    __half2 ll; ll.x = l0; ll.y = l1;
                    __half* r0 = g_A2 + (size_t)row * 1024 + col;
                    *(__half2*)(r0)       = hh;
                    *(__half2*)(r0 + 512) = ll;
                } else {
                    v0 += __ldg(&b2[col]);
                    v1 += __ldg(&b2[col + 1]);
                    if (col >= 256) {
                        *(float2*)(g_X2e + (size_t)row * 256 + (col - 256)) = make_float2(v0, v1);
                    } else {
                        __half h0 = __float2half_rn(v0);
                        __half h1 = __float2half_rn(v1);
                        __half l0 = __float2half_rn(v0 - __half2float(h0));
                        __half l1 = __float2half_rn(v1 - __half2float(h1));
                        __half2 hh; hh.x = h0; hh.y = h1;
                        __half2 ll; ll.x = l0; ll.y = l1;
                        __half* r0 = g_A3 + (size_t)row * 512 + col;
                        *(__half2*)(r0)       = hh;
                        *(__half2*)(r0 + 256) = ll;
                    }
                }
            }
        }
    }

    // release
    if (mode < 2) {
        __syncthreads();
        if (t == 0) {
            __threadfence();
            atomicAdd(mode == 0 ? &g_c1[mblk] : &g_c2[mblk], 1);
        }
    }
}

// ---------------- score + softmax + entropy (round-8 proven) ----------------
__global__ __launch_bounds__(256) void score_softmax(
    const float* __restrict__ X2e, const float* __restrict__ P,
    const float* __restrict__ emb_e, const float* __restrict__ mask,
    const int* __restrict__ r_space, const int* __restrict__ e_space,
    float* __restrict__ out_dist, float* __restrict__ out_ent, int write_ent)
{
    const int b = blockIdx.x;
    __shared__ float x2e[256];
    __shared__ float sc[KK];
    __shared__ float red1[8], red2[8], red3[8];
    const int t = threadIdx.x;
    const int warp = t >> 5, lane = t & 31;

    x2e[t] = X2e[b * 256 + t];
    const int   kidx = warp * 32 + lane;
    const int   eall = e_space[b * KK + kidx];
    const float mval = mask[b * KK + kidx];
    const unsigned validb = __ballot_sync(0xFFFFFFFFu, mval != 0.0f);
    __syncthreads();

    const float4 xa = *(const float4*)&x2e[lane * 4];
    const float4 xb = *(const float4*)&x2e[lane * 4 + 128];

    for (int i = 0; i < 32; i++) {
        const int k = warp * 32 + i;
        if ((validb >> i) & 1u) {
            const int e = __shfl_sync(0xFFFFFFFFu, eall, i);
            const float4* er = (const float4*)(emb_e + (size_t)e * 256);
            const float4 v0 = er[lane];
            const float4 v1 = er[lane + 32];
            float s = v0.x * xa.x + v0.y * xa.y + v0.z * xa.z + v0.w * xa.w
                    + v1.x * xb.x + v1.y * xb.y + v1.z * xb.z + v1.w * xb.w;
            #pragma unroll
            for (int o = 16; o; o >>= 1) s += __shfl_xor_sync(0xFFFFFFFFu, s, o);
            if (lane == 0) sc[k] = s;
        } else {
            if (lane == 0) sc[k] = 0.0f;
        }
    }
    __syncthreads();

    const int r = r_space[b * KK + t];
    float s = sc[t] + P[b * 512 + r] - (1.0f - mask[b * KK + t]) * 1e31f;

    float mx = s;
#pragma unroll
    for (int o = 16; o; o >>= 1) mx = fmaxf(mx, __shfl_xor_sync(0xFFFFFFFFu, mx, o));
    if (lane == 0) red1[warp] = mx;
    __syncthreads();
    float bm = red1[0];
#pragma unroll
    for (int w = 1; w < 8; w++) bm = fmaxf(bm, red1[w]);

    const float p = expf(s - bm);
    float sum = p;
#pragma unroll
    for (int o = 16; o; o >>= 1) sum += __shfl_xor_sync(0xFFFFFFFFu, sum, o);
    if (lane == 0) red2[warp] = sum;
    __syncthreads();
    float bs = 0.f;
#pragma unroll
    for (int w = 0; w < 8; w++) bs += red2[w];

    const float dist = p / bs;
    out_dist[b * KK + t] = dist;

    float es = -dist * logf(dist + 1e-20f);
#pragma unroll
    for (int o = 16; o; o >>= 1) es += __shfl_xor_sync(0xFFFFFFFFu, es, o);
    if (lane == 0) red3[warp] = es;
    __syncthreads();
    if (t == 0 && write_ent) {
        float tot = 0.f;
#pragma unroll
        for (int w = 0; w < 8; w++) tot += red3[w];
        out_ent[b] = tot;
    }
}

// ---------------- launcher ----------------
extern "C" void kernel_launch(void* const* d_in, const int* in_sizes, int n_in,
                              void* d_out, int out_size)
{
    const float* E     = (const float*)d_in[0];
    const float* H     = (const float*)d_in[1];
    const float* Q     = (const float*)d_in[2];
    const float* W1    = (const float*)d_in[3];
    const float* b1    = (const float*)d_in[4];
    const float* W2    = (const float*)d_in[5];
    const float* b2    = (const float*)d_in[6];
    const float* emb_r = (const float*)d_in[7];
    const float* emb_e = (const float*)d_in[8];
    const float* mask  = (const float*)d_in[9];
    const int*   r_sp  = (const int*)d_in[10];
    const int*   e_sp  = (const int*)d_in[11];
    float* out = (float*)d_out;

    __half *gA1, *gW1s, *gW2s, *gErs;
    float *gX2e, *gP;
    cudaGetSymbolAddress((void**)&gA1,  g_A1);
    cudaGetSymbolAddress((void**)&gW1s, g_W1s);
    cudaGetSymbolAddress((void**)&gW2s, g_W2s);
    cudaGetSymbolAddress((void**)&gErs, g_Ers);
    cudaGetSymbolAddress((void**)&gX2e, g_X2e);
    cudaGetSymbolAddress((void**)&gP,   g_P);

    cudaFuncSetAttribute(gemm_fused, cudaFuncAttributeMaxDynamicSharedMemorySize, GEMM_SMEM);

    const int write_ent = (out_size >= BB * KK + BB) ? 1 : 0;

    conv_all<<<(Q_TOT + 255) / 256, 256>>>(E, H, Q, W1, W2, emb_r, gA1, gW1s, gW2s, gErs);

    gemm_fused<<<768, 128, GEMM_SMEM>>>(b1, b2);

    score_softmax<<<BB, 256>>>(gX2e, gP, emb_e, mask, r_sp, e_sp,
                               out, out + (size_t)BB * KK, write_ent);
}

// round 15
// speedup vs baseline: 1.3427x; 1.0935x over previous
#include <cuda_runtime.h>
#include <cuda_fp16.h>
#include <math.h>
#include <stdint.h>

#define BB 2048
#define KK 256
#define AD 512
#define IN 768

// GEMM tiling: 64x64 CTA tile, 128 threads (4 warps, 32x32 each)
#define TM 64
#define TN 64
#define TKC 64                     // K-chunk (fp16 elems) = 128 B/row
#define NSTAGE 3
#define A_ST_B (TM * 128)          // 8192 B per stage
#define B_ST_B (TN * 128)          // 8192 B per stage
#define GEMM_SMEM (NSTAGE * (A_ST_B + B_ST_B))   // 49152 B

// ---------------- scratch (device globals: no allocs allowed) ----------------
// 2-term fp16 split: A-side [hi|lo], B-side [hi|hi]  (computes a . b_hi)
__device__ __half g_A1 [(size_t)BB * 1536];   // split concat(E,H,Q)
__device__ __half g_W1s[(size_t)AD * 1536];
__device__ __half g_A2 [(size_t)BB * 1024];   // split X (G1 out)
__device__ __half g_W2s[(size_t)AD * 1024];
__device__ __half g_A3 [(size_t)BB * 512];    // split X2[:, :256]
__device__ __half g_Ers[(size_t)512 * 512];   // split emb_r (rows 500..511 zero)
__device__ float g_X2e[(size_t)BB * 256];     // X2[:, 256:512] fp32
__device__ float g_P  [(size_t)BB * 512];     // X2[:, :256] @ emb_r^T

// ---------------- helpers ----------------
__device__ __forceinline__ uint32_t smem_u32(const void* p) {
    uint32_t a;
    asm("{ .reg .u64 t; cvta.to.shared.u64 t, %1; cvt.u32.u64 %0, t; }" : "=r"(a) : "l"(p));
    return a;
}
#define CP_ASYNC16(dst, src) \
    asm volatile("cp.async.cg.shared.global [%0], [%1], 16;" :: "r"(dst), "l"(src) : "memory")
#define CP_COMMIT()  asm volatile("cp.async.commit_group;" ::: "memory")
#define CP_WAIT(n)   asm volatile("cp.async.wait_group %0;" :: "n"(n) : "memory")

__device__ __forceinline__ void ldsm_x4(uint32_t* r, uint32_t addr) {
    asm volatile("ldmatrix.sync.aligned.m8n8.x4.shared.b16 {%0,%1,%2,%3}, [%4];"
                 : "=r"(r[0]), "=r"(r[1]), "=r"(r[2]), "=r"(r[3]) : "r"(addr));
}
__device__ __forceinline__ void mma16816(float* c, const uint32_t* a, const uint32_t* b) {
    asm volatile(
        "mma.sync.aligned.m16n8k16.row.col.f32.f16.f16.f32 "
        "{%0,%1,%2,%3}, {%4,%5,%6,%7}, {%8,%9}, {%0,%1,%2,%3};"
        : "+f"(c[0]), "+f"(c[1]), "+f"(c[2]), "+f"(c[3])
        : "r"(a[0]), "r"(a[1]), "r"(a[2]), "r"(a[3]), "r"(b[0]), "r"(b[1]));
}

// smem swizzle: 128B rows, 16B segs; seg' = seg ^ (row & 7)
__device__ __forceinline__ uint32_t swz(int row, int seg) {
    return (uint32_t)(row * 128 + ((seg ^ (row & 7)) << 4));
}

// A-side split: hi quad at d, lo quad at d+Koff
__device__ __forceinline__ void split_store_A(float4 v, __half* d, int Koff) {
    __align__(8) __half hh[4], ll[4];
    hh[0] = __float2half_rn(v.x); ll[0] = __float2half_rn(v.x - __half2float(hh[0]));
    hh[1] = __float2half_rn(v.y); ll[1] = __float2half_rn(v.y - __half2float(hh[1]));
    hh[2] = __float2half_rn(v.z); ll[2] = __float2half_rn(v.z - __half2float(hh[2]));
    hh[3] = __float2half_rn(v.w); ll[3] = __float2half_rn(v.w - __half2float(hh[3]));
    *(uint2*)d          = *(uint2*)hh;
    *(uint2*)(d + Koff) = *(uint2*)ll;
}
// B-side: hi quad duplicated at d and d+Koff
__device__ __forceinline__ void split_store_B(float4 v, __half* d, int Koff) {
    __align__(8) __half hh[4];
    hh[0] = __float2half_rn(v.x); hh[1] = __float2half_rn(v.y);
    hh[2] = __float2half_rn(v.z); hh[3] = __float2half_rn(v.w);
    *(uint2*)d          = *(uint2*)hh;
    *(uint2*)(d + Koff) = *(uint2*)hh;
}

// ---------------- fused conversion kernel ----------------
#define Q_R0 (BB * IN / 4)               // 393216
#define Q_R1 (Q_R0 + 512 * 768 / 4)      // 491520
#define Q_R2 (Q_R1 + 512 * 512 / 4)      // 557056
#define Q_TOT (Q_R2 + 512 * 256 / 4)     // 589824

__global__ __launch_bounds__(256) void conv_all(
    const float* __restrict__ E, const float* __restrict__ H, const float* __restrict__ Qm,
    const float* __restrict__ W1, const float* __restrict__ W2, const float* __restrict__ emb_r,
    __half* __restrict__ A1, __half* __restrict__ W1s,
    __half* __restrict__ W2s, __half* __restrict__ Ers)
{
    const int q = blockIdx.x * 256 + threadIdx.x;
    if (q < Q_R0) {
        const int m = q / 192, c = (q % 192) * 4;
        const float* src = (c < 256) ? (E + m * 256 + c)
                         : (c < 512) ? (H + m * 256 + (c - 256))
                                     : (Qm + m * 256 + (c - 512));
        float4 v = *(const float4*)src;
        split_store_A(v, A1 + (size_t)m * 1536 + c, 768);
    } else if (q < Q_R1) {
        const int q2 = q - Q_R0;
        const int n = q2 / 192, k = (q2 % 192) * 4;
        float4 v = *(const float4*)(W1 + (size_t)n * 768 + k);
        split_store_B(v, W1s + (size_t)n * 1536 + k, 768);
    } else if (q < Q_R2) {
        const int q2 = q - Q_R1;
        const int n = q2 / 128, k = (q2 % 128) * 4;
        float4 v = *(const float4*)(W2 + (size_t)n * 512 + k);
        split_store_B(v, W2s + (size_t)n * 1024 + k, 512);
    } else {
        const int q2 = q - Q_R2;
        const int n = q2 / 64, k = (q2 % 64) * 4;
        float4 v = make_float4(0.f, 0.f, 0.f, 0.f);
        if (n < 500) v = *(const float4*)(emb_r + (size_t)n * 256 + k);
        split_store_B(v, Ers + (size_t)n * 512 + k, 256);
    }
}

// ---------------- HMMA GEMM (64x64 tiles, 3-stage pipeline, swizzled smem) ----------------
// MODE 0: +b1, relu, split-store into g_A2 (W=512)
// MODE 1: +b2; cols<256 -> split into g_A3 (W=256); cols>=256 -> fp32 g_X2e
// MODE 2: fp32 -> g_P (stride 512)
template <int MODE>
__global__ __launch_bounds__(128) void gemm_mma(
    const __half* __restrict__ A, const __half* __restrict__ Bm,
    int ldk, int nchunks, const float* __restrict__ bias,
    __half* __restrict__ outs, float* __restrict__ outf)
{
    extern __shared__ __half sm[];
    const uint32_t smA = smem_u32(sm);
    const uint32_t smB = smA + NSTAGE * A_ST_B;

    const int t = threadIdx.x;
    const int warp = t >> 5, lane = t & 31;
    const int m0 = blockIdx.x * TM;
    const int n0 = blockIdx.y * TN;
    const int wm = (warp >> 1) * 32;       // 0 or 32
    const int wn = (warp & 1) * 32;        // 0 or 32

    const int rA  = lane & 15;
    const int sA8 = (lane >> 4);
    const int rB  = (lane & 7) + ((lane >> 4) & 1) * 8;
    const int sB8 = ((lane >> 3) & 1);

    float acc[2][4][4] = {};

    auto load_stage = [&](int s, int chunk) {
        const size_t k0 = (size_t)chunk * TKC;
        const uint32_t dA = smA + s * A_ST_B;
        const uint32_t dB = smB + s * B_ST_B;
        #pragma unroll
        for (int i = 0; i < 4; i++) {
            int v = t + i * 128;
            int row = v >> 3, seg = v & 7;
            CP_ASYNC16(dA + swz(row, seg),
                       A + (size_t)(m0 + row) * ldk + k0 + seg * 8);
        }
        #pragma unroll
        for (int i = 0; i < 4; i++) {
            int v = t + i * 128;
            int row = v >> 3, seg = v & 7;
            CP_ASYNC16(dB + swz(row, seg),
                       Bm + (size_t)(n0 + row) * ldk + k0 + seg * 8);
        }
        CP_COMMIT();
    };

    load_stage(0, 0);
    load_stage(1, 1);

    for (int i = 0; i < nchunks; i++) {
        CP_WAIT(1);
        __syncthreads();
        if (i + 2 < nchunks) load_stage((i + 2) % NSTAGE, i + 2);
        else CP_COMMIT();                                   // keep pending-count invariant

        const uint32_t sAst = smA + (i % NSTAGE) * A_ST_B;
        const uint32_t sBst = smB + (i % NSTAGE) * B_ST_B;
        #pragma unroll
        for (int ks = 0; ks < 4; ks++) {
            uint32_t a0[4], a1[4], b0[4], b1[4];
            const int segK = ks * 2;
            ldsm_x4(a0, sAst + swz(wm +      rA, segK + sA8));
            ldsm_x4(a1, sAst + swz(wm + 16 + rA, segK + sA8));
            ldsm_x4(b0, sBst + swz(wn +      rB, segK + sB8));
            ldsm_x4(b1, sBst + swz(wn + 16 + rB, segK + sB8));
            #pragma unroll
            for (int mi = 0; mi < 2; mi++) {
                const uint32_t* aa = mi ? a1 : a0;
                mma16816(acc[mi][0], aa, b0 + 0);
                mma16816(acc[mi][1], aa, b0 + 2);
                mma16816(acc[mi][2], aa, b1 + 0);
                mma16816(acc[mi][3], aa, b1 + 2);
            }
        }
    }

    // ---------------- epilogue ----------------
    #pragma unroll
    for (int mi = 0; mi < 2; mi++) {
        #pragma unroll
        for (int h = 0; h < 2; h++) {
            const int row = m0 + wm + 16 * mi + 8 * h + (lane >> 2);
            #pragma unroll
            for (int j = 0; j < 4; j++) {
                const int col = n0 + wn + 8 * j + 2 * (lane & 3);
                float v0 = acc[mi][j][2 * h];
                float v1 = acc[mi][j][2 * h + 1];
                if (MODE == 2) {
                    *(float2*)(outf + (size_t)row * 512 + col) = make_float2(v0, v1);
                } else {
                    v0 += __ldg(&bias[col]);
                    v1 += __ldg(&bias[col + 1]);
                    if (MODE == 0) { v0 = fmaxf(v0, 0.0f); v1 = fmaxf(v1, 0.0f); }
                    if (MODE == 1 && col >= 256) {
                        *(float2*)(outf + (size_t)row * 256 + (col - 256)) = make_float2(v0, v1);
                    } else {
                        const int W = (MODE == 0) ? 512 : 256;   // A-side split [hi|lo]
                        __half h0 = __float2half_rn(v0);
                        __half h1 = __float2half_rn(v1);
                        __half l0 = __float2half_rn(v0 - __half2float(h0));
                        __half l1 = __float2half_rn(v1 - __half2float(h1));
                        __half2 hh; hh.x = h0; hh.y = h1;
                        __half2 ll; ll.x = l0; ll.y = l1;
                        __half* r0 = outs + (size_t)row * (2 * W) + col;
                        *(__half2*)(r0)     = hh;
                        *(__half2*)(r0 + W) = ll;
                    }
                }
            }
        }
    }
}

// ---------------- score + softmax + entropy (mask-skipped, 2-way unrolled dot) ----------------
__global__ __launch_bounds__(256) void score_softmax(
    const float* __restrict__ X2e, const float* __restrict__ P,
    const float* __restrict__ emb_e, const float* __restrict__ mask,
    const int* __restrict__ r_space, const int* __restrict__ e_space,
    float* __restrict__ out_dist, float* __restrict__ out_ent, int write_ent)
{
    const int b = blockIdx.x;
    __shared__ float x2e[256];
    __shared__ float sc[KK];
    __shared__ float red1[8], red2[8], red3[8];
    const int t = threadIdx.x;
    const int warp = t >> 5, lane = t & 31;

    x2e[t] = X2e[b * 256 + t];
    const int   kidx = warp * 32 + lane;
    const int   eall = e_space[b * KK + kidx];
    const float mval = mask[b * KK + kidx];
    const unsigned validb = __ballot_sync(0xFFFFFFFFu, mval != 0.0f);
    __syncthreads();

    const float4 xa = *(const float4*)&x2e[lane * 4];
    const float4 xb = *(const float4*)&x2e[lane * 4 + 128];

    // two k's per iteration: independent shfl-reduce chains + doubled load MLP
    for (int i = 0; i < 32; i += 2) {
        const int k0 = warp * 32 + i;
        const bool va = (validb >> i) & 1u;
        const bool vb = (validb >> (i + 1)) & 1u;
        float s0 = 0.0f, s1 = 0.0f;
        if (va) {
            const int e0 = __shfl_sync(0xFFFFFFFFu, eall, i);
            const float4* er = (const float4*)(emb_e + (size_t)e0 * 256);
            const float4 v0 = er[lane];
            const float4 v1 = er[lane + 32];
            s0 = v0.x * xa.x + v0.y * xa.y + v0.z * xa.z + v0.w * xa.w
               + v1.x * xb.x + v1.y * xb.y + v1.z * xb.z + v1.w * xb.w;
        }
        if (vb) {
            const int e1 = __shfl_sync(0xFFFFFFFFu, eall, i + 1);
            const float4* er = (const float4*)(emb_e + (size_t)e1 * 256);
            const float4 v0 = er[lane];
            const float4 v1 = er[lane + 32];
            s1 = v0.x * xa.x + v0.y * xa.y + v0.z * xa.z + v0.w * xa.w
               + v1.x * xb.x + v1.y * xb.y + v1.z * xb.z + v1.w * xb.w;
        }
        #pragma unroll
        for (int o = 16; o; o >>= 1) {
            s0 += __shfl_xor_sync(0xFFFFFFFFu, s0, o);
            s1 += __shfl_xor_sync(0xFFFFFFFFu, s1, o);
        }
        if (lane == 0) { sc[k0] = s0; sc[k0 + 1] = s1; }
    }
    __syncthreads();

    const int r = r_space[b * KK + t];
    float s = sc[t] + P[b * 512 + r] - (1.0f - mask[b * KK + t]) * 1e31f;

    float mx = s;
#pragma unroll
    for (int o = 16; o; o >>= 1) mx = fmaxf(mx, __shfl_xor_sync(0xFFFFFFFFu, mx, o));
    if (lane == 0) red1[warp] = mx;
    __syncthreads();
    float bm = red1[0];
#pragma unroll
    for (int w = 1; w < 8; w++) bm = fmaxf(bm, red1[w]);

    const float p = expf(s - bm);
    float sum = p;
#pragma unroll
    for (int o = 16; o; o >>= 1) sum += __shfl_xor_sync(0xFFFFFFFFu, sum, o);
    if (lane == 0) red2[warp] = sum;
    __syncthreads();
    float bs = 0.f;
#pragma unroll
    for (int w = 0; w < 8; w++) bs += red2[w];

    const float dist = p / bs;
    out_dist[b * KK + t] = dist;

    float es = -dist * logf(dist + 1e-20f);
#pragma unroll
    for (int o = 16; o; o >>= 1) es += __shfl_xor_sync(0xFFFFFFFFu, es, o);
    if (lane == 0) red3[warp] = es;
    __syncthreads();
    if (t == 0 && write_ent) {
        float tot = 0.f;
#pragma unroll
        for (int w = 0; w < 8; w++) tot += red3[w];
        out_ent[b] = tot;
    }
}

// ---------------- launcher ----------------
extern "C" void kernel_launch(void* const* d_in, const int* in_sizes, int n_in,
                              void* d_out, int out_size)
{
    const float* E     = (const float*)d_in[0];
    const float* H     = (const float*)d_in[1];
    const float* Q     = (const float*)d_in[2];
    const float* W1    = (const float*)d_in[3];
    const float* b1    = (const float*)d_in[4];
    const float* W2    = (const float*)d_in[5];
    const float* b2    = (const float*)d_in[6];
    const float* emb_r = (const float*)d_in[7];
    const float* emb_e = (const float*)d_in[8];
    const float* mask  = (const float*)d_in[9];
    const int*   r_sp  = (const int*)d_in[10];
    const int*   e_sp  = (const int*)d_in[11];
    float* out = (float*)d_out;

    __half *gA1, *gW1s, *gA2, *gW2s, *gA3, *gErs;
    float *gX2e, *gP;
    cudaGetSymbolAddress((void**)&gA1,  g_A1);
    cudaGetSymbolAddress((void**)&gW1s, g_W1s);
    cudaGetSymbolAddress((void**)&gA2,  g_A2);
    cudaGetSymbolAddress((void**)&gW2s, g_W2s);
    cudaGetSymbolAddress((void**)&gA3,  g_A3);
    cudaGetSymbolAddress((void**)&gErs, g_Ers);
    cudaGetSymbolAddress((void**)&gX2e, g_X2e);
    cudaGetSymbolAddress((void**)&gP,   g_P);

    cudaFuncSetAttribute(gemm_mma<0>, cudaFuncAttributeMaxDynamicSharedMemorySize, GEMM_SMEM);
    cudaFuncSetAttribute(gemm_mma<1>, cudaFuncAttributeMaxDynamicSharedMemorySize, GEMM_SMEM);
    cudaFuncSetAttribute(gemm_mma<2>, cudaFuncAttributeMaxDynamicSharedMemorySize, GEMM_SMEM);

    const int write_ent = (out_size >= BB * KK + BB) ? 1 : 0;

    conv_all<<<Q_TOT / 256, 256>>>(E, H, Q, W1, W2, emb_r, gA1, gW1s, gW2s, gErs);

    gemm_mma<0><<<dim3(BB / TM, AD / TN), 128, GEMM_SMEM>>>(gA1, gW1s, 1536, 24, b1, gA2, nullptr);
    gemm_mma<1><<<dim3(BB / TM, AD / TN), 128, GEMM_SMEM>>>(gA2, gW2s, 1024, 16, b2, gA3, gX2e);
    gemm_mma<2><<<dim3(BB / TM, AD / TN), 128, GEMM_SMEM>>>(gA3, gErs,  512,  8, nullptr, nullptr, gP);

    score_softmax<<<BB, 256>>>(gX2e, gP, emb_e, mask, r_sp, e_sp,
                               out, out + (size_t)BB * KK, write_ent);
}